// round 4
// baseline (speedup 1.0000x reference)
#include <cuda_runtime.h>
#include <math.h>
#include <stdint.h>

#define BB   32
#define SS   256
#define NN   50
#define DD   100
#define QDIM 768

#define NT   13      // n-tiles (104 cols: 100 W rows + w~ row + pad)
#define KT   13      // k-tiles (104 of 128.. 100 used)
#define MT   7       // m-tiles (112 rows: 100 used)
#define PAIRS_PER_BLK 4
#define LSTR 28      // per-lane B-frag stride in floats (13 kt * 2 + 2 pad)

// per-batch: w~ = W^T Qn, c = Qn.Vb, and B fragments
__device__ float g_wt[BB * DD];
__device__ float g_cb[BB];
__device__ float g_Bf[BB * NT * 32 * LSTR];   // [b][nt][lane][28]

// ---------------------------------------------------------------------------
__device__ __forceinline__ void mma_tf32(float c[4], const float* a,
                                         float b0, float b1)
{
    asm volatile(
        "mma.sync.aligned.m16n8k8.row.col.f32.tf32.tf32.f32 "
        "{%0,%1,%2,%3}, {%4,%5,%6,%7}, {%8,%9}, {%0,%1,%2,%3};\n"
        : "+f"(c[0]), "+f"(c[1]), "+f"(c[2]), "+f"(c[3])
        : "r"(__float_as_uint(a[0])), "r"(__float_as_uint(a[1])),
          "r"(__float_as_uint(a[2])), "r"(__float_as_uint(a[3])),
          "r"(__float_as_uint(b0)),  "r"(__float_as_uint(b1)));
}

// fragment-layout offsets (in floats)
__device__ __forceinline__ int afrag_off(int r, int d) {
    int mt = r >> 4, rr = r & 15, g = rr & 7, half = rr >> 3;
    int kt = d >> 3, c = d & 7, tg = c & 3, sec = c >> 2;
    return ((mt * KT + kt) * 32 + (g * 4 + tg)) * 4 + half + 2 * sec;
}
__device__ __forceinline__ int bfrag_off(int n, int d) {
    int nt = n >> 3, g = n & 7;
    int kt = d >> 3, c = d & 7, tg = c & 3, sec = c >> 2;
    return (nt * 32 + g * 4 + tg) * LSTR + kt * 2 + sec;
}

// ---------------------------------------------------------------------------
// Kernel 1: Qn = normalize(q @ Qw^T + Qb); g_wt = Vw^T Qn ; g_cb = Qn . Vb
// ---------------------------------------------------------------------------
__global__ __launch_bounds__(256) void qproj_kernel(
    const float* __restrict__ q,
    const float* __restrict__ Qw,
    const float* __restrict__ Qb,
    const float* __restrict__ Vw,
    const float* __restrict__ Vb)
{
    int b = blockIdx.x;
    __shared__ float sq[QDIM];
    __shared__ float sQ[DD];
    __shared__ float red[8];

    int tid  = threadIdx.x;
    int warp = tid >> 5;
    int lane = tid & 31;

    for (int j = tid; j < QDIM; j += 256) sq[j] = q[b * QDIM + j];
    __syncthreads();

    for (int e = warp; e < DD; e += 8) {
        const float* wrow = Qw + (size_t)e * QDIM;
        float acc = 0.f;
        for (int j = lane; j < QDIM; j += 32) acc += sq[j] * wrow[j];
        #pragma unroll
        for (int o = 16; o; o >>= 1) acc += __shfl_xor_sync(0xffffffffu, acc, o);
        if (lane == 0) sQ[e] = acc + Qb[e];
    }
    __syncthreads();

    float ss = 0.f;
    for (int e = tid; e < DD; e += 256) ss += sQ[e] * sQ[e];
    #pragma unroll
    for (int o = 16; o; o >>= 1) ss += __shfl_xor_sync(0xffffffffu, ss, o);
    if (lane == 0) red[warp] = ss;
    __syncthreads();
    if (tid == 0) {
        float t = 0.f;
        #pragma unroll
        for (int w = 0; w < 8; w++) t += red[w];
        red[0] = fmaxf(sqrtf(t), 1e-12f);
    }
    __syncthreads();
    float inv = 1.0f / red[0];
    for (int e = tid; e < DD; e += 256) sQ[e] *= inv;
    __syncthreads();

    for (int d = tid; d < DD; d += 256) {
        float acc = 0.f;
        #pragma unroll 4
        for (int e = 0; e < DD; e++) acc += sQ[e] * Vw[e * DD + d];
        g_wt[b * DD + d] = acc;
    }
    if (warp == 0) {
        float acc = 0.f;
        for (int e = lane; e < DD; e += 32) acc += sQ[e] * Vb[e];
        #pragma unroll
        for (int o = 16; o; o >>= 1) acc += __shfl_xor_sync(0xffffffffu, acc, o);
        if (lane == 0) g_cb[b] = acc;
    }
}

// ---------------------------------------------------------------------------
// Kernel 1b: build B fragments per batch.
// B GEMM row n: n<100 -> W[n][:], n==100 -> w~_b, else 0.  col d>=100 -> 0.
// Bf[b][nt][lane][2k+s] = Brow(nt*8 + lane>>2)[k*8 + (lane&3) + 4*s]
// ---------------------------------------------------------------------------
__global__ __launch_bounds__(256) void bfrag_kernel(
    const float* __restrict__ Vw)
{
    int b = blockIdx.x;
    float* dst = g_Bf + b * NT * 32 * LSTR;
    for (int i = threadIdx.x; i < NT * 32 * (LSTR / 2); i += 256) {
        int slot = i % (LSTR / 2);          // 0..13 (13 = pad)
        int rem  = i / (LSTR / 2);
        int lane = rem & 31;
        int nt   = rem >> 5;
        float v0 = 0.f, v1 = 0.f;
        if (slot < KT) {
            int g = lane >> 2, tg = lane & 3;
            int n  = nt * 8 + g;
            int d0 = slot * 8 + tg;
            int d1 = d0 + 4;
            const float* row = 0;
            if (n < 100)       row = Vw + n * DD;
            else if (n == 100) row = g_wt + b * DD;
            if (row) {
                if (d0 < 100) v0 = row[d0];
                if (d1 < 100) v1 = row[d1];
            }
        }
        dst[(nt * 32 + lane) * LSTR + slot * 2 + 0] = v0;
        dst[(nt * 32 + lane) * LSTR + slot * 2 + 1] = v1;
    }
}

// ---------------------------------------------------------------------------
// Kernel 2: fragment-order tf32 mma.sync GEMM; 4 s-pairs per block
// ---------------------------------------------------------------------------
#define AF_FLOATS (MT * KT * 32 * 4)        // 11648
#define BF_FLOATS (NT * 32 * LSTR)          // 11648
#define F_AF    0
#define F_BF    (F_AF + AF_FLOATS)
#define F_VB    (F_BF + BF_FLOATS)          // 104
#define F_NORM  (F_VB + 104)                // 112
#define F_DOT   (F_NORM + 112)              // 112
#define F_ATT   (F_DOT + 112)               // 128
#define F_T     (F_ATT + 128)               // 256
#define F_MISC  (F_T + 256)                 // 8
#define SMEM_FLOATS_TOT (F_MISC + 8)

__global__ __launch_bounds__(256, 2) void attn_kernel(
    const float* __restrict__ v,
    const float* __restrict__ Vb,
    float* __restrict__ out)
{
    extern __shared__ float smf[];
    float* sAf   = smf + F_AF;
    float* sBf   = smf + F_BF;
    float* sVb   = smf + F_VB;
    float* snorm = smf + F_NORM;
    float* sdot  = smf + F_DOT;
    float* sAtt  = smf + F_ATT;
    float* st    = smf + F_T;
    float* sMisc = smf + F_MISC;

    int tid  = threadIdx.x;
    int warp = tid >> 5;
    int lane = tid & 31;

    int blk   = blockIdx.x;                  // 1024
    int b     = blk >> 5;
    int pair0 = (blk & 31) * PAIRS_PER_BLK;

    // ---- prologue: zero A frags (pad), stage B frags + bias + cb ----
    {
        float4 z = make_float4(0.f, 0.f, 0.f, 0.f);
        float4* pa = (float4*)sAf;
        for (int i = tid; i < AF_FLOATS / 4; i += 256) pa[i] = z;
        const float4* gsrc = (const float4*)(g_Bf + b * BF_FLOATS);
        float4* pb = (float4*)sBf;
        for (int i = tid; i < BF_FLOATS / 4; i += 256) pb[i] = gsrc[i];
    }
    if (tid < 104) sVb[tid] = (tid < 100) ? Vb[tid] : 0.f;
    if (tid == 128) sMisc[0] = g_cb[b];

    for (int p = 0; p < PAIRS_PER_BLK; p++) {
        __syncthreads();

        // stage A = v tile (100x100) into fragment order
        size_t vbase = (size_t)(b * 128 + pair0 + p) * 10000;
        for (int c = tid; c < 2500; c += 256) {
            int r = c / 25, dq = (c - r * 25) * 4;
            float4 val = *(const float4*)(v + vbase + r * DD + dq);
            int mt = r >> 4, rr = r & 15, g = rr & 7, half = rr >> 3;
            int kt = dq >> 3, sec = (dq & 7) >> 2;
            int base = ((mt * KT + kt) * 32 + g * 4) * 4 + half + 2 * sec;
            sAf[base +  0] = val.x;
            sAf[base +  4] = val.y;
            sAf[base +  8] = val.z;
            sAf[base + 12] = val.w;
        }
        __syncthreads();

        // ---- GEMM: warps 0..6, one 16-row m-tile each ----
        if (warp < 7) {
            int g = lane >> 2, tg = lane & 3;
            int mrow = warp * 16 + g;
            float cb = sMisc[0];

            float4 aR[KT];
            {
                const float4* afp = (const float4*)sAf + warp * KT * 32 + lane;
                #pragma unroll
                for (int kt = 0; kt < KT; kt++) aR[kt] = afp[kt * 32];
            }
            float sq0 = 0.f, sq1 = 0.f;
            #pragma unroll 1
            for (int nt = 0; nt < NT; nt++) {
                const float* bl = sBf + (nt * 32 + lane) * LSTR;
                float bb[LSTR];
                #pragma unroll
                for (int q2 = 0; q2 < LSTR / 4; q2++)
                    *(float4*)(bb + q2 * 4) = *(const float4*)(bl + q2 * 4);

                float c[4] = {0.f, 0.f, 0.f, 0.f};
                #pragma unroll
                for (int kt = 0; kt < KT; kt++)
                    mma_tf32(c, (const float*)&aR[kt], bb[2 * kt], bb[2 * kt + 1]);

                int col0 = nt * 8 + 2 * tg;
                if (col0 < 100) {
                    float bia = sVb[col0];
                    float k0 = c[0] + bia; sq0 += k0 * k0;
                    float k2 = c[2] + bia; sq1 += k2 * k2;
                }
                if (col0 + 1 < 100) {
                    float bia = sVb[col0 + 1];
                    float k1 = c[1] + bia; sq0 += k1 * k1;
                    float k3 = c[3] + bia; sq1 += k3 * k3;
                }
                if (nt == NT - 1 && tg == 2) {       // col 100 = numerator
                    if (mrow < 100)     sdot[mrow]     = c[0] + cb;
                    if (mrow + 8 < 100) sdot[mrow + 8] = c[2] + cb;
                }
            }
            sq0 += __shfl_xor_sync(0xffffffffu, sq0, 1);
            sq0 += __shfl_xor_sync(0xffffffffu, sq0, 2);
            sq1 += __shfl_xor_sync(0xffffffffu, sq1, 1);
            sq1 += __shfl_xor_sync(0xffffffffu, sq1, 2);
            if (tg == 0) {
                if (mrow < 100)     snorm[mrow]     = sq0;
                if (mrow + 8 < 100) snorm[mrow + 8] = sq1;
            }
        }
        __syncthreads();

        // ---- softmax per s (warps 0,1) ----
        if (warp < 2) {
            int s = warp;
            int rb = s * 50;
            float x0, x1;
            {
                int r = rb + lane;
                float l2 = sqrtf(snorm[r]);
                if (l2 == 0.0f) l2 = 1e-6f;
                float sc = sdot[r] / l2;
                sc = (sc == 0.0f) ? -10000.0f : sc;
                x0 = (sc > 0.0f) ? sc : 0.01f * sc;
            }
            x1 = -INFINITY;
            if (lane < NN - 32) {
                int r = rb + lane + 32;
                float l2 = sqrtf(snorm[r]);
                if (l2 == 0.0f) l2 = 1e-6f;
                float sc = sdot[r] / l2;
                sc = (sc == 0.0f) ? -10000.0f : sc;
                x1 = (sc > 0.0f) ? sc : 0.01f * sc;
            }
            float m = fmaxf(x0, x1);
            #pragma unroll
            for (int o = 16; o; o >>= 1) m = fmaxf(m, __shfl_xor_sync(0xffffffffu, m, o));
            float e0 = expf(x0 - m);
            float e1 = (lane < NN - 32) ? expf(x1 - m) : 0.0f;
            float sm = e0 + e1;
            #pragma unroll
            for (int o = 16; o; o >>= 1) sm += __shfl_xor_sync(0xffffffffu, sm, o);
            float inv = 1.0f / sm;
            float a0 = e0 * inv;
            if (a0 == (1.0f / 50.0f)) a0 = 0.0f;
            float a1 = 0.0f;
            if (lane < NN - 32) {
                a1 = e1 * inv;
                if (a1 == (1.0f / 50.0f)) a1 = 0.0f;
            }
            sAtt[rb + lane] = a0;
            if (lane < NN - 32) sAtt[rb + lane + 32] = a1;
            float sg = a0 + a1;
            #pragma unroll
            for (int o = 16; o; o >>= 1) sg += __shfl_xor_sync(0xffffffffu, sg, o);
            if (lane == 0) sMisc[1 + s] = sg;
        }
        __syncthreads();

        // ---- t[s][d] = sum_n att[s][n] * v[s*50+n][d] (read A frags) ----
        int s = tid >> 7;
        int d = tid & 127;
        if (d < 100) {
            float acc = 0.f;
            const float* ab = sAtt + s * 50;
            #pragma unroll 2
            for (int n = 0; n < NN; n++)
                acc += ab[n] * sAf[afrag_off(s * 50 + n, d)];
            st[s * 128 + d] = acc;
        }
        __syncthreads();

        // ---- out[s][e] = sum_d t[s][d] * W[e][d] + sigma_s * Vb[e] ----
        if (d < 100) {
            float acc = sMisc[1 + s] * sVb[d];
            const float* tp = st + s * 128;
            #pragma unroll 4
            for (int dd = 0; dd < DD; dd++)
                acc += tp[dd] * sBf[bfrag_off(d, dd)];
            out[(size_t)(b * 128 + pair0 + p) * 200 + s * 100 + d] = acc;
        }
    }
}

// ---------------------------------------------------------------------------
extern "C" void kernel_launch(void* const* d_in, const int* in_sizes, int n_in,
                              void* d_out, int out_size)
{
    // metadata order: input_ent, q, k, v, Q_w, Q_b, V_w, V_b
    const float* q  = (const float*)d_in[1];
    const float* v  = (const float*)d_in[3];
    const float* Qw = (const float*)d_in[4];
    const float* Qb = (const float*)d_in[5];
    const float* Vw = (const float*)d_in[6];
    const float* Vb = (const float*)d_in[7];
    float* out = (float*)d_out;

    qproj_kernel<<<BB, 256>>>(q, Qw, Qb, Vw, Vb);
    bfrag_kernel<<<BB, 256>>>(Vw);

    size_t smem_bytes = SMEM_FLOATS_TOT * sizeof(float);
    cudaFuncSetAttribute(attn_kernel, cudaFuncAttributeMaxDynamicSharedMemorySize,
                         (int)smem_bytes);
    attn_kernel<<<BB * SS / 2 / PAIRS_PER_BLK, 256, smem_bytes>>>(v, Vb, out);
}

// round 5
// speedup vs baseline: 2.0650x; 2.0650x over previous
#include <cuda_runtime.h>
#include <math.h>
#include <stdint.h>

#define BB   32
#define SS   256
#define NN   50
#define DD   100
#define QDIM 768

#define NT   13      // n-tiles (104 cols: 100 W rows + w~ row + pad)
#define KT   13      // k-tiles (104 cols of A, 100 used)
#define AP   108     // A/K smem row stride (floats), conflict-free
#define LSTR 28      // per-lane B-frag stride (13 kt * 2 + 2 pad)
#define PAIRS_PER_BLK 2

__device__ float g_Qraw[BB * DD];
__device__ float g_cb[BB];
__device__ float g_Bf[BB * NT * 32 * LSTR];   // [b][nt][lane][28]

// ---------------------------------------------------------------------------
__device__ __forceinline__ void mma_tf32(float c[4], const float* a,
                                         float b0, float b1)
{
    asm volatile(
        "mma.sync.aligned.m16n8k8.row.col.f32.tf32.tf32.f32 "
        "{%0,%1,%2,%3}, {%4,%5,%6,%7}, {%8,%9}, {%0,%1,%2,%3};\n"
        : "+f"(c[0]), "+f"(c[1]), "+f"(c[2]), "+f"(c[3])
        : "r"(__float_as_uint(a[0])), "r"(__float_as_uint(a[1])),
          "r"(__float_as_uint(a[2])), "r"(__float_as_uint(a[3])),
          "r"(__float_as_uint(b0)),  "r"(__float_as_uint(b1)));
}

// ---------------------------------------------------------------------------
// Kernel 1a: g_Qraw[b][e] = q[b] . Qw[e] + Qb[e]   (grid 3200, coalesced)
// ---------------------------------------------------------------------------
__global__ __launch_bounds__(128) void qproj_a(
    const float* __restrict__ q,
    const float* __restrict__ Qw,
    const float* __restrict__ Qb)
{
    int b = blockIdx.x / DD, e = blockIdx.x % DD;
    __shared__ float red[4];
    const float* qr = q + (size_t)b * QDIM;
    const float* wr = Qw + (size_t)e * QDIM;
    int tid = threadIdx.x, warp = tid >> 5, lane = tid & 31;

    float acc = 0.f;
    #pragma unroll 6
    for (int i = tid; i < QDIM; i += 128) acc += qr[i] * wr[i];
    #pragma unroll
    for (int o = 16; o; o >>= 1) acc += __shfl_xor_sync(0xffffffffu, acc, o);
    if (lane == 0) red[warp] = acc;
    __syncthreads();
    if (tid == 0)
        g_Qraw[b * DD + e] = red[0] + red[1] + red[2] + red[3] + Qb[e];
}

// ---------------------------------------------------------------------------
// Kernel 1b: per batch: normalize Q, w~ = Vw^T Qn, cb = Qn.Vb, build B frags
// ---------------------------------------------------------------------------
__global__ __launch_bounds__(128) void qproj_b(
    const float* __restrict__ Vw,
    const float* __restrict__ Vb)
{
    int b = blockIdx.x;
    __shared__ float sQ[DD];
    __shared__ float sWq[DD];
    __shared__ float red[4];

    int tid = threadIdx.x, warp = tid >> 5, lane = tid & 31;

    float qv = (tid < DD) ? g_Qraw[b * DD + tid] : 0.f;
    float ss = qv * qv;
    #pragma unroll
    for (int o = 16; o; o >>= 1) ss += __shfl_xor_sync(0xffffffffu, ss, o);
    if (lane == 0) red[warp] = ss;
    __syncthreads();
    if (tid == 0)
        red[0] = fmaxf(sqrtf(red[0] + red[1] + red[2] + red[3]), 1e-12f);
    __syncthreads();
    float inv = 1.0f / red[0];
    if (tid < DD) sQ[tid] = qv * inv;
    __syncthreads();

    // w~_d = sum_e Qn[e] * Vw[e][d]  (coalesced over d)
    if (tid < DD) {
        float a = 0.f;
        #pragma unroll 4
        for (int e = 0; e < DD; e++) a += sQ[e] * Vw[e * DD + tid];
        sWq[tid] = a;
    }
    // cb
    if (warp == 0) {
        float a = 0.f;
        for (int e = lane; e < DD; e += 32) a += sQ[e] * Vb[e];
        #pragma unroll
        for (int o = 16; o; o >>= 1) a += __shfl_xor_sync(0xffffffffu, a, o);
        if (lane == 0) g_cb[b] = a;
    }
    __syncthreads();

    // build B fragments: rows 0..99 = W rows, row 100 = w~, else 0
    float* dst = g_Bf + (size_t)b * NT * 32 * LSTR;
    for (int i = tid; i < NT * 32 * (LSTR / 2); i += 128) {
        int slot = i % (LSTR / 2);
        int rem  = i / (LSTR / 2);
        int ln   = rem & 31;
        int nt   = rem >> 5;
        float v0 = 0.f, v1 = 0.f;
        if (slot < KT) {
            int g = ln >> 2, tg = ln & 3;
            int n  = nt * 8 + g;
            int d0 = slot * 8 + tg;
            int d1 = d0 + 4;
            if (n < 100) {
                if (d0 < 100) v0 = Vw[n * DD + d0];
                if (d1 < 100) v1 = Vw[n * DD + d1];
            } else if (n == 100) {
                if (d0 < 100) v0 = sWq[d0];
                if (d1 < 100) v1 = sWq[d1];
            }
        }
        dst[(nt * 32 + ln) * LSTR + slot * 2 + 0] = v0;
        dst[(nt * 32 + ln) * LSTR + slot * 2 + 1] = v1;
    }
}

// ---------------------------------------------------------------------------
// Kernel 2: per block = (b, 2 s-pairs). tf32 mma GEMM computes K (stored back
// over the A tile) + score numerator (col 100). out = att @ K.
// ---------------------------------------------------------------------------
#define AK_FLOATS (112 * AP)                // 12096 (A tile, later K)
#define BF_FLOATS (NT * 32 * LSTR)          // 11648
#define F_AK    0
#define F_BF    (F_AK + AK_FLOATS)
#define F_VB    (F_BF + BF_FLOATS)          // 104
#define F_NORM  (F_VB + 104)                // 112
#define F_DOT   (F_NORM + 112)              // 112
#define F_ATT   (F_DOT + 112)               // 128
#define F_MISC  (F_ATT + 128)               // 8
#define SMEM_FLOATS_TOT (F_MISC + 8)

__global__ __launch_bounds__(256, 2) void attn_kernel(
    const float* __restrict__ v,
    const float* __restrict__ Vb,
    float* __restrict__ out)
{
    extern __shared__ float smf[];
    float* sAK   = smf + F_AK;      // A tile, overwritten by K
    float* sBf   = smf + F_BF;
    float* sVb   = smf + F_VB;
    float* snorm = smf + F_NORM;
    float* sdot  = smf + F_DOT;
    float* sAtt  = smf + F_ATT;
    float* sMisc = smf + F_MISC;

    int tid  = threadIdx.x;
    int warp = tid >> 5;
    int lane = tid & 31;

    int blk   = blockIdx.x;                  // 2048 blocks
    int b     = blk >> 6;                    // 64 blocks per batch
    int pair0 = (blk & 63) * PAIRS_PER_BLK;

    // ---- prologue: zero A tile (pads persist), stage B frags, bias, cb ----
    {
        float4 z = make_float4(0.f, 0.f, 0.f, 0.f);
        float4* pa = (float4*)sAK;
        for (int i = tid; i < AK_FLOATS / 4; i += 256) pa[i] = z;
        const float4* gsrc = (const float4*)(g_Bf + (size_t)b * BF_FLOATS);
        float4* pb = (float4*)sBf;
        for (int i = tid; i < BF_FLOATS / 4; i += 256) pb[i] = gsrc[i];
    }
    if (tid < 104) sVb[tid] = (tid < 100) ? Vb[tid] : 0.f;
    if (tid == 128) sMisc[0] = g_cb[b];

    for (int p = 0; p < PAIRS_PER_BLK; p++) {
        __syncthreads();

        // ---- stage A = v tile (100 rows x 100 cols), float4 ----
        size_t vbase = (size_t)(b * 128 + pair0 + p) * 10000;
        for (int c = tid; c < 2500; c += 256) {
            int r = c / 25, dq = (c - r * 25) * 4;
            float4 val = *(const float4*)(v + vbase + r * DD + dq);
            *(float4*)(sAK + r * AP + dq) = val;
        }
        __syncthreads();

        // ---- GEMM: warps 0..6, 16-row m-tile each; K written back ----
        if (warp < 7) {
            int g = lane >> 2, tg = lane & 3;
            int mrow = warp * 16 + g;
            float cb = sMisc[0];

            // gather A fragments (conflict-free scalar LDS), rows mrow/mrow+8
            float aR[KT][4];
            {
                const float* a0p = sAK + mrow * AP;
                const float* a1p = sAK + (mrow + 8) * AP;
                #pragma unroll
                for (int kt = 0; kt < KT; kt++) {
                    int k0 = kt * 8;
                    aR[kt][0] = a0p[k0 + tg];
                    aR[kt][1] = a1p[k0 + tg];
                    aR[kt][2] = a0p[k0 + tg + 4];
                    aR[kt][3] = a1p[k0 + tg + 4];
                }
            }
            float sq0 = 0.f, sq1 = 0.f;
            #pragma unroll 1
            for (int nt = 0; nt < NT; nt++) {
                const float4* bl = (const float4*)(sBf + (nt * 32 + lane) * LSTR);
                float c[4] = {0.f, 0.f, 0.f, 0.f};
                #pragma unroll
                for (int j = 0; j < 6; j++) {
                    float4 B4 = bl[j];
                    mma_tf32(c, aR[2 * j],     B4.x, B4.y);
                    mma_tf32(c, aR[2 * j + 1], B4.z, B4.w);
                }
                {
                    float4 B4 = bl[6];
                    mma_tf32(c, aR[12], B4.x, B4.y);
                }
                // K = c + bias; accumulate norms; store K over A rows
                int col0 = nt * 8 + 2 * tg;
                if (col0 < 100) {
                    float bia = sVb[col0];
                    float k0 = c[0] + bia, k2 = c[2] + bia;
                    sq0 += k0 * k0;  sq1 += k2 * k2;
                    if (mrow < 100)     sAK[mrow * AP + col0]       = k0;
                    if (mrow + 8 < 100) sAK[(mrow + 8) * AP + col0] = k2;
                }
                if (col0 + 1 < 100) {
                    float bia = sVb[col0 + 1];
                    float k1 = c[1] + bia, k3 = c[3] + bia;
                    sq0 += k1 * k1;  sq1 += k3 * k3;
                    if (mrow < 100)     sAK[mrow * AP + col0 + 1]       = k1;
                    if (mrow + 8 < 100) sAK[(mrow + 8) * AP + col0 + 1] = k3;
                }
                if (nt == NT - 1 && tg == 2) {     // col 100 = numerator
                    if (mrow < 100)     sdot[mrow]     = c[0] + cb;
                    if (mrow + 8 < 100) sdot[mrow + 8] = c[2] + cb;
                }
            }
            sq0 += __shfl_xor_sync(0xffffffffu, sq0, 1);
            sq0 += __shfl_xor_sync(0xffffffffu, sq0, 2);
            sq1 += __shfl_xor_sync(0xffffffffu, sq1, 1);
            sq1 += __shfl_xor_sync(0xffffffffu, sq1, 2);
            if (tg == 0) {
                if (mrow < 100)     snorm[mrow]     = sq0;
                if (mrow + 8 < 100) snorm[mrow + 8] = sq1;
            }
        }
        __syncthreads();

        // ---- softmax per s (warps 0,1) ----
        if (warp < 2) {
            int s = warp;
            int rb = s * 50;
            float x0, x1;
            {
                int r = rb + lane;
                float l2 = sqrtf(snorm[r]);
                if (l2 == 0.0f) l2 = 1e-6f;
                float sc = sdot[r] / l2;
                sc = (sc == 0.0f) ? -10000.0f : sc;
                x0 = (sc > 0.0f) ? sc : 0.01f * sc;
            }
            x1 = -INFINITY;
            if (lane < NN - 32) {
                int r = rb + lane + 32;
                float l2 = sqrtf(snorm[r]);
                if (l2 == 0.0f) l2 = 1e-6f;
                float sc = sdot[r] / l2;
                sc = (sc == 0.0f) ? -10000.0f : sc;
                x1 = (sc > 0.0f) ? sc : 0.01f * sc;
            }
            float m = fmaxf(x0, x1);
            #pragma unroll
            for (int o = 16; o; o >>= 1) m = fmaxf(m, __shfl_xor_sync(0xffffffffu, m, o));
            float e0 = expf(x0 - m);
            float e1 = (lane < NN - 32) ? expf(x1 - m) : 0.0f;
            float sm = e0 + e1;
            #pragma unroll
            for (int o = 16; o; o >>= 1) sm += __shfl_xor_sync(0xffffffffu, sm, o);
            float inv = 1.0f / sm;
            float a0 = e0 * inv;
            if (a0 == (1.0f / 50.0f)) a0 = 0.0f;
            float a1 = 0.0f;
            if (lane < NN - 32) {
                a1 = e1 * inv;
                if (a1 == (1.0f / 50.0f)) a1 = 0.0f;
            }
            sAtt[rb + lane] = a0;
            if (lane < NN - 32) sAtt[rb + lane + 32] = a1;
        }
        __syncthreads();

        // ---- out[s][e] = sum_n att[s][n] * K[s*50+n][e]  (K in sAK) ----
        int s = tid >> 7;
        int e = tid & 127;
        if (e < 100) {
            float acc = 0.f;
            const float* ab = sAtt + s * 50;
            const float* kb = sAK + (s * 50) * AP + e;
            #pragma unroll 5
            for (int n = 0; n < NN; n++) acc += ab[n] * kb[n * AP];
            out[(size_t)(b * 128 + pair0 + p) * 200 + s * 100 + e] = acc;
        }
    }
}

// ---------------------------------------------------------------------------
extern "C" void kernel_launch(void* const* d_in, const int* in_sizes, int n_in,
                              void* d_out, int out_size)
{
    // metadata order: input_ent, q, k, v, Q_w, Q_b, V_w, V_b
    const float* q  = (const float*)d_in[1];
    const float* v  = (const float*)d_in[3];
    const float* Qw = (const float*)d_in[4];
    const float* Qb = (const float*)d_in[5];
    const float* Vw = (const float*)d_in[6];
    const float* Vb = (const float*)d_in[7];
    float* out = (float*)d_out;

    qproj_a<<<BB * DD, 128>>>(q, Qw, Qb);
    qproj_b<<<BB, 128>>>(Vw, Vb);

    size_t smem_bytes = SMEM_FLOATS_TOT * sizeof(float);
    cudaFuncSetAttribute(attn_kernel, cudaFuncAttributeMaxDynamicSharedMemorySize,
                         (int)smem_bytes);
    attn_kernel<<<BB * SS / 2 / PAIRS_PER_BLK, 256, smem_bytes>>>(v, Vb, out);
}